// round 10
// baseline (speedup 1.0000x reference)
#include <cuda_runtime.h>
#include <cuda_fp16.h>
#include <cstdint>
#include <math.h>

#define NLY 8
#define Hd 768
#define Ed 1536
#define Nst 16
#define Rr 4
#define Kc 4
#define Cc 3
#define Bb 2
#define Ll 2048
#define Mrows (Bb*Ll)        // 4096
#define DBC (Rr+2*Nst)       // 36
#define TWO_E (2*Ed)         // 3072
#define MH ((size_t)Mrows*Hd)

// ======================= scratch (device globals) ============================
__device__ float g_hs  [Mrows*Hd];
__device__ float g_proj[Mrows*TWO_E];
__device__ float g_u   [Mrows*Ed];
__device__ float g_dbc [Mrows*DBC];
__device__ float g_acc3[3*Mrows*Hd];

// fp16 weights, transposed to [N,K]
__device__ __align__(16) __half g_wi [NLY*TWO_E*Hd];
__device__ __align__(16) __half g_wo [NLY*Hd*Ed];
__device__ __align__(16) __half g_wf [NLY*Cc*Hd*Hd];
// xproj weights padded to [l][64][1536], fp16 two-limb
__device__ __align__(16) __half g_wxh[NLY*64*Ed];
__device__ __align__(16) __half g_wxl[NLY*64*Ed];
// fp16 activations
__device__ __align__(16) __half g_xq [Mrows*Ed];    // x | ys
__device__ __align__(16) __half g_hq [Mrows*Hd];    // hs (fp16 copy)
__device__ __align__(16) __half g_yb3[3*Mrows*Hd];  // fractal stage 1
__device__ __align__(16) __half g_xq3[3*Mrows*Hd];  // fractal stage 2
// u two-limb for xp_gemm
__device__ __align__(16) __half g_uh [Mrows*Ed];
__device__ __align__(16) __half g_ul [Mrows*Ed];

// ======================= helpers =============================================
__device__ __forceinline__ uint32_t smem_u32(const void* p) {
    uint32_t a;
    asm("{ .reg .u64 t; cvta.to.shared.u64 t, %1; cvt.u32.u64 %0, t; }" : "=r"(a) : "l"(p));
    return a;
}
__device__ __forceinline__ void cp_async16(uint32_t dst, const void* src) {
    asm volatile("cp.async.cg.shared.global [%0], [%1], 16;" :: "r"(dst), "l"(src) : "memory");
}
__device__ __forceinline__ void cp_commit() {
    asm volatile("cp.async.commit_group;" ::: "memory");
}
__device__ __forceinline__ void ldm_x4(uint32_t* r, uint32_t addr) {
    asm volatile("ldmatrix.sync.aligned.m8n8.x4.shared.b16 {%0,%1,%2,%3}, [%4];"
                 : "=r"(r[0]), "=r"(r[1]), "=r"(r[2]), "=r"(r[3]) : "r"(addr));
}
__device__ __forceinline__ void mma_f16(float* d, const uint32_t* a, uint32_t b0, uint32_t b1) {
    asm volatile("mma.sync.aligned.m16n8k16.row.col.f32.f16.f16.f32 "
                 "{%0,%1,%2,%3}, {%4,%5,%6,%7}, {%8,%9}, {%0,%1,%2,%3};"
                 : "+f"(d[0]), "+f"(d[1]), "+f"(d[2]), "+f"(d[3])
                 : "r"(a[0]), "r"(a[1]), "r"(a[2]), "r"(a[3]), "r"(b0), "r"(b1));
}

// ======================= small kernels =======================================
__global__ void embed_kernel(const int* __restrict__ ids, const float* __restrict__ tok,
                             const float* __restrict__ pos, float* __restrict__ hs)
{
    int idx = blockIdx.x*blockDim.x + threadIdx.x;
    if (idx >= Mrows*Hd) return;
    int h = idx % Hd;
    int m = idx / Hd;
    int l = m % Ll;
    int id = ids[m];
    hs[idx] = tok[(size_t)id*Hd + h] + pos[(size_t)l*Hd + h];
}

// LayerNorm (+optional hs += (acc3[0]+acc3[1]+acc3[2])/6); output fp32 or fp16.
template<int HASACC, int OUTH>
__global__ void ln_fused(float* __restrict__ hs, const float* __restrict__ acc3,
                         const float* __restrict__ w, const float* __restrict__ b,
                         float* __restrict__ out32, __half* __restrict__ oh)
{
    int row = blockIdx.x;
    size_t base = (size_t)row*Hd;
    int tid = threadIdx.x;
    float v[3];
    float s = 0.f, s2 = 0.f;
    #pragma unroll
    for (int q = 0; q < 3; q++) {
        int i = tid + q*256;
        float t = hs[base + i];
        if (HASACC) {
            t += (0.5f/3.0f)*(acc3[base + i] + acc3[MH + base + i] + acc3[2*MH + base + i]);
            hs[base + i] = t;
        }
        v[q] = t;
        s += t; s2 += t*t;
    }
    #pragma unroll
    for (int o = 16; o; o >>= 1) {
        s  += __shfl_xor_sync(0xffffffffu, s,  o);
        s2 += __shfl_xor_sync(0xffffffffu, s2, o);
    }
    __shared__ float sa[8], sb[8];
    __shared__ float sh_mean, sh_inv;
    int wi = tid >> 5;
    if ((tid & 31) == 0) { sa[wi] = s; sb[wi] = s2; }
    __syncthreads();
    if (tid == 0) {
        float ts = 0.f, t2 = 0.f;
        #pragma unroll
        for (int i = 0; i < 8; i++) { ts += sa[i]; t2 += sb[i]; }
        float m  = ts / (float)Hd;
        float var = t2 / (float)Hd - m*m;
        sh_mean = m;
        sh_inv  = rsqrtf(var + 1e-5f);
    }
    __syncthreads();
    float mean = sh_mean, inv = sh_inv;
    #pragma unroll
    for (int q = 0; q < 3; q++) {
        int i = tid + q*256;
        float y = (v[q] - mean) * inv * w[i] + b[i];
        if (OUTH) oh[base + i] = __float2half(y);
        else      out32[base + i] = y;
    }
}

// W[z][K][N] fp32 -> T[z][N][K] fp16
__global__ void wtrans(const float* __restrict__ W, __half* __restrict__ T, int K, int N)
{
    __shared__ float t[32][33];
    size_t moff = (size_t)blockIdx.z * K * N;
    int nx = blockIdx.x*32, kx = blockIdx.y*32;
    int tx = threadIdx.x, ty = threadIdx.y;
    #pragma unroll
    for (int r = 0; r < 32; r += 8)
        t[ty + r][tx] = W[moff + (size_t)(kx + ty + r)*N + nx + tx];
    __syncthreads();
    #pragma unroll
    for (int r = 0; r < 32; r += 8)
        T[moff + (size_t)(nx + ty + r)*K + kx + tx] = __float2half(t[tx][ty + r]);
}

// xproj weights: [l][1536][36] fp32 -> padded [l][64][1536] fp16 hi/lo
__global__ void wxpad(const float* __restrict__ xw, __half* __restrict__ Th,
                      __half* __restrict__ Tl)
{
    int idx = blockIdx.x*256 + threadIdx.x;
    if (idx >= NLY*64*Ed) return;
    int k = idx % Ed;
    int n = (idx / Ed) % 64;
    int l = idx / (Ed*64);
    float v = (n < DBC) ? xw[((size_t)l*Ed + k)*DBC + n] : 0.f;
    __half h = __float2half(v);
    Th[idx] = h;
    Tl[idx] = __float2half(v - __half2float(h));
}

// ======================= fp16 mma GEMM (fat warp tiles, z-batched) ===========
// C = act( A[M,K] @ B[N,K]^T + bias [+add] ),  A,B fp16 K-major.
// CTA tile 128x128, BK=64, 4 warps (64x64 each), 3-stage cp.async, 2 CTAs/SM.
// blockIdx.z selects batch slice via strides Az/Bz/Oz/biasZ.
#define HSTAGE 32768
#define HSMEM  (3*HSTAGE)

template<int ACT, int HASADD, int OUTF32, int OUTH>
__global__ __launch_bounds__(128, 2)
void h_gemm(const __half* __restrict__ A, const __half* __restrict__ B,
            const float* __restrict__ bias, const float* __restrict__ add,
            float* __restrict__ C, __half* __restrict__ Oh, int M, int K, int N,
            size_t Az, size_t Bz, size_t Oz, size_t biasZ)
{
    extern __shared__ __align__(16) char smem[];
    const uint32_t sb0 = smem_u32(smem);
    int tid = threadIdx.x, lane = tid & 31, wid = tid >> 5;
    int zb = blockIdx.z;
    A += (size_t)zb*Az;  B += (size_t)zb*Bz;  bias += (size_t)zb*biasZ;
    int m0 = blockIdx.y << 7, n0 = blockIdx.x << 7;
    int wm = (wid >> 1) * 64, wn = (wid & 1) * 64;

    const __half* gsrc[2] = { A + (size_t)m0*K, B + (size_t)n0*K };

    const int cr0 = tid >> 3;
    const int cch = tid & 7;
    const int csw = cch ^ (cr0 & 7);
    const uint32_t cso = (uint32_t)(cr0*128 + csw*16);

    float acc[4][8][4];
    #pragma unroll
    for (int t = 0; t < 4; t++)
        #pragma unroll
        for (int j = 0; j < 8; j++)
            #pragma unroll
            for (int e = 0; e < 4; e++) acc[t][j][e] = 0.f;

    const int nt = K >> 6;

    #pragma unroll
    for (int p = 0; p < 2; p++) {
        uint32_t st = sb0 + p*HSTAGE;
        int k0 = p << 6;
        #pragma unroll
        for (int mat = 0; mat < 2; mat++) {
            const __half* src = gsrc[mat] + k0;
            uint32_t sbase = st + mat*16384u;
            #pragma unroll
            for (int q = 0; q < 8; q++) {
                int row = q*16 + cr0;
                cp_async16(sbase + cso + (uint32_t)(q*2048),
                           src + (size_t)row*K + cch*8);
            }
        }
        cp_commit();
    }

    int rA = (lane & 7) + ((lane >> 3) & 1)*8;
    int hi = lane >> 4;

    int stage = 0, pstage = 2;
    for (int i = 0; i < nt; i++) {
        if (i == nt - 1) asm volatile("cp.async.wait_group 0;" ::: "memory");
        else             asm volatile("cp.async.wait_group 1;" ::: "memory");
        __syncthreads();

        uint32_t stA = sb0 + stage*HSTAGE;
        uint32_t stB = stA + 16384u;

        #pragma unroll
        for (int s = 0; s < 4; s++) {
            int ck = 2*s + hi;
            uint32_t bf[4][4];
            #pragma unroll
            for (int u = 0; u < 4; u++) {
                int row = wn + u*16 + rA;
                uint32_t off = (uint32_t)(row*128 + ((ck ^ (row & 7))<<4));
                ldm_x4(bf[u], stB + off);
            }
            #pragma unroll
            for (int t = 0; t < 4; t++) {
                int row = wm + t*16 + rA;
                uint32_t off = (uint32_t)(row*128 + ((ck ^ (row & 7))<<4));
                uint32_t af[4];
                ldm_x4(af, stA + off);
                #pragma unroll
                for (int j = 0; j < 8; j++) {
                    int u = j >> 1, w = j & 1;
                    mma_f16(acc[t][j], af, bf[u][w], bf[u][w+2]);
                }
            }
        }

        if (i + 2 < nt) {
            uint32_t stp = sb0 + pstage*HSTAGE;
            int k0 = (i + 2) << 6;
            #pragma unroll
            for (int mat = 0; mat < 2; mat++) {
                const __half* src = gsrc[mat] + k0;
                uint32_t sbase = stp + mat*16384u;
                #pragma unroll
                for (int q = 0; q < 8; q++) {
                    int row = q*16 + cr0;
                    cp_async16(sbase + cso + (uint32_t)(q*2048),
                               src + (size_t)row*K + cch*8);
                }
            }
            cp_commit();
        }
        stage = (stage + 1 == 3) ? 0 : stage + 1;
        pstage = (pstage + 1 == 3) ? 0 : pstage + 1;
    }

    // ---- epilogue ----
    #pragma unroll
    for (int t = 0; t < 4; t++) {
        int mrow = m0 + wm + t*16 + (lane >> 2);
        #pragma unroll
        for (int j = 0; j < 8; j++) {
            int col = n0 + wn + j*8 + 2*(lane & 3);
            float b0 = bias[col], b1 = bias[col+1];
            #pragma unroll
            for (int half = 0; half < 2; half++) {
                int row = mrow + half*8;
                float v0 = acc[t][j][half*2+0] + b0;
                float v1 = acc[t][j][half*2+1] + b1;
                size_t o = (size_t)row*N + col;
                if (HASADD) { v0 += add[o]; v1 += add[o+1]; }
                if (ACT) {
                    v0 = v0 / (1.f + __expf(-v0));
                    v1 = v1 / (1.f + __expf(-v1));
                }
                if (OUTF32) *(float2*)(C + (size_t)zb*Oz + o) = make_float2(v0, v1);
                if (OUTH) {
                    __half2 hh;
                    hh.x = __float2half(v0);
                    hh.y = __float2half(v1);
                    *(__half2*)(Oh + (size_t)zb*Oz + o) = hh;
                }
            }
        }
    }
}

// ======================= xproj GEMM (fp16 two-limb, N=64 pad) ================
// dbc[M,36] = (uh+ul)[M,K] @ (wh+wl)[64,K]^T  (cols >= 36 discarded)
// CTA tile 128x64, 4 warps (32x64 each), K=1536, 3-stage.
// stage: Ah(16K) Al(16K) Bh(8K) Bl(8K) = 48KB; 3 stages = 144KB.
#define XSTAGE 49152
#define XSMEM  (3*XSTAGE)

__global__ __launch_bounds__(128, 1)
void xp_gemm(const __half* __restrict__ Auh, const __half* __restrict__ Aul,
             const __half* __restrict__ Bh_, const __half* __restrict__ Bl_,
             float* __restrict__ dbc, int K)
{
    extern __shared__ __align__(16) char smem[];
    const uint32_t sb0 = smem_u32(smem);
    int tid = threadIdx.x, lane = tid & 31, wid = tid >> 5;
    int m0 = blockIdx.y << 7;
    int wm = wid * 32;

    const __half* gA[2] = { Auh + (size_t)m0*K, Aul + (size_t)m0*K };
    const __half* gB[2] = { Bh_, Bl_ };

    const int cr0 = tid >> 3;
    const int cch = tid & 7;
    const int csw = cch ^ (cr0 & 7);
    const uint32_t cso = (uint32_t)(cr0*128 + csw*16);

    float acc[2][8][4];
    #pragma unroll
    for (int t = 0; t < 2; t++)
        #pragma unroll
        for (int j = 0; j < 8; j++)
            #pragma unroll
            for (int e = 0; e < 4; e++) acc[t][j][e] = 0.f;

    const int nt = K >> 6;

    #pragma unroll
    for (int p = 0; p < 2; p++) {
        uint32_t st = sb0 + p*XSTAGE;
        int k0 = p << 6;
        #pragma unroll
        for (int mat = 0; mat < 2; mat++) {
            const __half* src = gA[mat] + k0;
            uint32_t sbase = st + mat*16384u;
            #pragma unroll
            for (int q = 0; q < 8; q++) {
                int row = q*16 + cr0;
                cp_async16(sbase + cso + (uint32_t)(q*2048),
                           src + (size_t)row*K + cch*8);
            }
        }
        #pragma unroll
        for (int mat = 0; mat < 2; mat++) {
            const __half* src = gB[mat] + k0;
            uint32_t sbase = st + 32768u + mat*8192u;
            #pragma unroll
            for (int q = 0; q < 4; q++) {
                int row = q*16 + cr0;
                cp_async16(sbase + cso + (uint32_t)(q*2048),
                           src + (size_t)row*K + cch*8);
            }
        }
        cp_commit();
    }

    int rA = (lane & 7) + ((lane >> 3) & 1)*8;
    int hi = lane >> 4;

    int stage = 0, pstage = 2;
    for (int i = 0; i < nt; i++) {
        if (i == nt - 1) asm volatile("cp.async.wait_group 0;" ::: "memory");
        else             asm volatile("cp.async.wait_group 1;" ::: "memory");
        __syncthreads();

        uint32_t stAh = sb0 + stage*XSTAGE;
        uint32_t stAl = stAh + 16384u;
        uint32_t stBh = stAh + 32768u;
        uint32_t stBl = stAh + 40960u;

        #pragma unroll
        for (int s = 0; s < 4; s++) {
            int ck = 2*s + hi;
            uint32_t bh[4][4], bl[4][4];
            #pragma unroll
            for (int u = 0; u < 4; u++) {
                int row = u*16 + rA;
                uint32_t off = (uint32_t)(row*128 + ((ck ^ (row & 7))<<4));
                ldm_x4(bh[u], stBh + off);
                ldm_x4(bl[u], stBl + off);
            }
            #pragma unroll
            for (int t = 0; t < 2; t++) {
                int row = wm + t*16 + rA;
                uint32_t off = (uint32_t)(row*128 + ((ck ^ (row & 7))<<4));
                uint32_t afh[4], afl[4];
                ldm_x4(afh, stAh + off);
                ldm_x4(afl, stAl + off);
                #pragma unroll
                for (int j = 0; j < 8; j++) {
                    int u = j >> 1, w = j & 1;
                    mma_f16(acc[t][j], afh, bh[u][w], bh[u][w+2]);
                    mma_f16(acc[t][j], afh, bl[u][w], bl[u][w+2]);
                    mma_f16(acc[t][j], afl, bh[u][w], bh[u][w+2]);
                }
            }
        }

        if (i + 2 < nt) {
            uint32_t stp = sb0 + pstage*XSTAGE;
            int k0 = (i + 2) << 6;
            #pragma unroll
            for (int mat = 0; mat < 2; mat++) {
                const __half* src = gA[mat] + k0;
                uint32_t sbase = stp + mat*16384u;
                #pragma unroll
                for (int q = 0; q < 8; q++) {
                    int row = q*16 + cr0;
                    cp_async16(sbase + cso + (uint32_t)(q*2048),
                               src + (size_t)row*K + cch*8);
                }
            }
            #pragma unroll
            for (int mat = 0; mat < 2; mat++) {
                const __half* src = gB[mat] + k0;
                uint32_t sbase = stp + 32768u + mat*8192u;
                #pragma unroll
                for (int q = 0; q < 4; q++) {
                    int row = q*16 + cr0;
                    cp_async16(sbase + cso + (uint32_t)(q*2048),
                               src + (size_t)row*K + cch*8);
                }
            }
            cp_commit();
        }
        stage = (stage + 1 == 3) ? 0 : stage + 1;
        pstage = (pstage + 1 == 3) ? 0 : pstage + 1;
    }

    // ---- epilogue: keep only cols < 36 ----
    #pragma unroll
    for (int t = 0; t < 2; t++) {
        int mrow = m0 + wm + t*16 + (lane >> 2);
        #pragma unroll
        for (int j = 0; j < 8; j++) {
            int col = j*8 + 2*(lane & 3);
            if (col < DBC) {
                #pragma unroll
                for (int half = 0; half < 2; half++) {
                    int row = mrow + half*8;
                    *(float2*)(dbc + (size_t)row*DBC + col) =
                        make_float2(acc[t][j][half*2+0], acc[t][j][half*2+1]);
                }
            }
        }
    }
}

// ======================= conv / scan =========================================
// causal dwconv + silu; emits u fp32 + fp16 two-limb (uh, ul)
__global__ void conv_silu(const float* __restrict__ proj, const float* __restrict__ cw,
                          const float* __restrict__ cb, float* __restrict__ u,
                          __half* __restrict__ uh, __half* __restrict__ ul)
{
    int idx = blockIdx.x*blockDim.x + threadIdx.x;
    if (idx >= Mrows*Ed) return;
    int e = idx % Ed;
    int m = idx / Ed;
    int l = m % Ll;
    float w0 = cw[e*4+0], w1 = cw[e*4+1], w2 = cw[e*4+2], w3 = cw[e*4+3];
    float v = cb[e];
    const float* base = proj + (size_t)m*TWO_E + e;
    if (l >= 3) v += base[-3*TWO_E]*w0;
    if (l >= 2) v += base[-2*TWO_E]*w1;
    if (l >= 1) v += base[-1*TWO_E]*w2;
    v += base[0]*w3;
    float s = v / (1.f + __expf(-v));
    u[idx] = s;
    __half h = __float2half(s);
    uh[idx] = h;
    ul[idx] = __float2half(s - __half2float(h));
}

// Selective scan; ys emitted as fp16.
__global__ void scan_kernel(const float* __restrict__ u, const float* __restrict__ dbc,
                            const float* __restrict__ proj,
                            const float* __restrict__ dt_w, const float* __restrict__ dt_b,
                            const float* __restrict__ A_log, const float* __restrict__ Dv,
                            __half* __restrict__ ys)
{
    int gw = (blockIdx.x*blockDim.x + threadIdx.x) >> 5;
    int lane = threadIdx.x & 31;
    int ch = gw*2 + (lane >> 4);
    int b = ch / Ed, e = ch - b*Ed;
    int n = lane & 15;

    float Ac = -__expf(A_log[e*Nst + n]);
    float Dc = Dv[e];
    float w0 = dt_w[e], w1 = dt_w[Ed + e], w2 = dt_w[2*Ed + e], w3 = dt_w[3*Ed + e];
    float dtb = dt_b[e];

    const float* up = u    + (size_t)b*Ll*Ed + e;
    const float* dp = dbc  + (size_t)b*Ll*DBC;
    const float* gp = proj + (size_t)b*Ll*TWO_E + Ed + e;
    size_t ybase = (size_t)b*Ll*Ed + e;

    float h = 0.f;
    for (int t0 = 0; t0 < Ll; t0 += 4) {
        float p[4], uq[4];
        #pragma unroll
        for (int q = 0; q < 4; q++) {
            int t = t0 + q;
            const float* dr = dp + t*DBC;
            float4 d4 = *(const float4*)dr;
            float xdt = d4.x*w0 + d4.y*w1 + d4.z*w2 + d4.w*w3 + dtb;
            float dtv = (xdt > 20.f) ? xdt : log1pf(__expf(xdt));
            float uv = up[(size_t)t*Ed];
            float bt = dr[Rr + n];
            float ct = dr[Rr + Nst + n];
            h = h*__expf(dtv*Ac) + (dtv*uv)*bt;
            p[q] = h*ct;
            uq[q] = uv;
        }
        #pragma unroll
        for (int q = 0; q < 4; q++) {
            p[q] += __shfl_xor_sync(0xffffffffu, p[q], 8);
            p[q] += __shfl_xor_sync(0xffffffffu, p[q], 4);
            p[q] += __shfl_xor_sync(0xffffffffu, p[q], 2);
            p[q] += __shfl_xor_sync(0xffffffffu, p[q], 1);
        }
        if (n == 0) {
            #pragma unroll
            for (int q = 0; q < 4; q++) {
                int t = t0 + q;
                float g = gp[(size_t)t*TWO_E];
                float y = (p[q] + uq[q]*Dc) / (1.f + __expf(-g));
                ys[ybase + (size_t)t*Ed] = __float2half(y);
            }
        }
    }
}

// ======================= launch ==============================================
extern "C" void kernel_launch(void* const* d_in, const int* in_sizes, int n_in,
                              void* d_out, int out_size)
{
    const int*   ids     = (const int*)  d_in[0];
    const float* tok_emb = (const float*)d_in[1];
    const float* pos_emb = (const float*)d_in[2];
    const float* ln_w    = (const float*)d_in[3];
    const float* ln_b    = (const float*)d_in[4];
    const float* in_w    = (const float*)d_in[5];
    const float* in_b    = (const float*)d_in[6];
    const float* conv_w  = (const float*)d_in[7];
    const float* conv_b  = (const float*)d_in[8];
    const float* xproj_w = (const float*)d_in[9];
    const float* dt_w    = (const float*)d_in[10];
    const float* dt_b    = (const float*)d_in[11];
    const float* A_log   = (const float*)d_in[12];
    const float* Dv      = (const float*)d_in[13];
    const float* out_w   = (const float*)d_in[14];
    const float* out_b   = (const float*)d_in[15];
    const float* frac_w  = (const float*)d_in[16];
    const float* frac_b  = (const float*)d_in[17];
    const float* fln_w   = (const float*)d_in[18];
    const float* fln_b   = (const float*)d_in[19];

    float *hs, *proj, *u, *dbc, *acc3;
    __half *wi, *wo, *wf, *wxh, *wxl, *xq, *hq, *yb3, *xq3, *uh, *ul;
    cudaGetSymbolAddress((void**)&hs,   g_hs);
    cudaGetSymbolAddress((void**)&proj, g_proj);
    cudaGetSymbolAddress((void**)&u,    g_u);
    cudaGetSymbolAddress((void**)&dbc,  g_dbc);
    cudaGetSymbolAddress((void**)&acc3, g_acc3);
    cudaGetSymbolAddress((void**)&wi,   g_wi);
    cudaGetSymbolAddress((void**)&wo,   g_wo);
    cudaGetSymbolAddress((void**)&wf,   g_wf);
    cudaGetSymbolAddress((void**)&wxh,  g_wxh);
    cudaGetSymbolAddress((void**)&wxl,  g_wxl);
    cudaGetSymbolAddress((void**)&xq,   g_xq);
    cudaGetSymbolAddress((void**)&hq,   g_hq);
    cudaGetSymbolAddress((void**)&yb3,  g_yb3);
    cudaGetSymbolAddress((void**)&xq3,  g_xq3);
    cudaGetSymbolAddress((void**)&uh,   g_uh);
    cudaGetSymbolAddress((void**)&ul,   g_ul);

    cudaFuncSetAttribute(h_gemm<0,0,1,0>, cudaFuncAttributeMaxDynamicSharedMemorySize, HSMEM);
    cudaFuncSetAttribute(h_gemm<0,1,1,1>, cudaFuncAttributeMaxDynamicSharedMemorySize, HSMEM);
    cudaFuncSetAttribute(h_gemm<1,0,0,1>, cudaFuncAttributeMaxDynamicSharedMemorySize, HSMEM);
    cudaFuncSetAttribute(h_gemm<1,0,1,0>, cudaFuncAttributeMaxDynamicSharedMemorySize, HSMEM);
    cudaFuncSetAttribute(xp_gemm, cudaFuncAttributeMaxDynamicSharedMemorySize, XSMEM);

    // one-time weight prep
    wtrans<<<dim3(TWO_E/32, Hd/32, NLY), dim3(32,8)>>>(in_w, wi, Hd, TWO_E);
    wtrans<<<dim3(Hd/32, Ed/32, NLY),    dim3(32,8)>>>(out_w, wo, Ed, Hd);
    wtrans<<<dim3(Hd/32, Hd/32, NLY*Cc), dim3(32,8)>>>(frac_w, wf, Hd, Hd);
    wxpad<<<(NLY*64*Ed + 255)/256, 256>>>(xproj_w, wxh, wxl);

    embed_kernel<<<(Mrows*Hd + 255)/256, 256>>>(ids, tok_emb, pos_emb, hs);

    for (int l = 0; l < NLY; l++) {
        // x = LN(hs [+ sum(acc3)/6]) -> fp16
        if (l == 0)
            ln_fused<0,1><<<Mrows, 256>>>(hs, nullptr,
                ln_w + (size_t)l*Hd, ln_b + (size_t)l*Hd, nullptr, xq);
        else
            ln_fused<1,1><<<Mrows, 256>>>(hs, acc3,
                ln_w + (size_t)l*Hd, ln_b + (size_t)l*Hd, nullptr, xq);

        // proj = x @ in_w + in_b (fp32)
        h_gemm<0,0,1,0><<<dim3(TWO_E/128, Mrows/128, 1), 128, HSMEM>>>(
            xq, wi + (size_t)l*TWO_E*Hd, in_b + (size_t)l*TWO_E, nullptr,
            proj, nullptr, Mrows, Hd, TWO_E, 0, 0, 0, 0);

        conv_silu<<<(Mrows*Ed + 255)/256, 256>>>(
            proj, conv_w + (size_t)l*Ed*Kc, conv_b + (size_t)l*Ed, u, uh, ul);

        // dbc = u @ xproj_w  (fp16 two-limb tensor-core GEMM)
        xp_gemm<<<dim3(1, Mrows/128), 128, XSMEM>>>(
            uh, ul, wxh + (size_t)l*64*Ed, wxl + (size_t)l*64*Ed, dbc, Ed);

        // scan -> ys fp16 (into xq)
        scan_kernel<<<192, 256>>>(u, dbc, proj,
            dt_w + (size_t)l*Rr*Ed, dt_b + (size_t)l*Ed,
            A_log + (size_t)l*Ed*Nst, Dv + (size_t)l*Ed, xq);

        // hs = ys @ out_w + out_b + hs (fp32) ; also hq = fp16(hs)
        h_gemm<0,1,1,1><<<dim3(Hd/128, Mrows/128, 1), 128, HSMEM>>>(
            xq, wo + (size_t)l*Hd*Ed, out_b + (size_t)l*Hd, hs,
            hs, hq, Mrows, Ed, Hd, 0, 0, 0, 0);

        // fractal: z-batched over the 3 independent chains
        const __half* fwl = wf + (size_t)l*Cc*Hd*Hd;
        const float*  fbl = frac_b + (size_t)l*Cc*Hd;
        h_gemm<1,0,0,1><<<dim3(Hd/128, Mrows/128, Cc), 128, HSMEM>>>(
            hq, fwl, fbl, nullptr, nullptr, yb3,
            Mrows, Hd, Hd, 0, (size_t)Hd*Hd, MH, Hd);
        h_gemm<1,0,0,1><<<dim3(Hd/128, Mrows/128, Cc), 128, HSMEM>>>(
            yb3, fwl, fbl, nullptr, nullptr, xq3,
            Mrows, Hd, Hd, MH, (size_t)Hd*Hd, MH, Hd);
        h_gemm<1,0,1,0><<<dim3(Hd/128, Mrows/128, Cc), 128, HSMEM>>>(
            xq3, fwl, fbl, nullptr, acc3, nullptr,
            Mrows, Hd, Hd, MH, (size_t)Hd*Hd, MH, Hd);
    }

    // final: hs += sum(acc3)/6 ; out = LN(hs)
    ln_fused<1,0><<<Mrows, 256>>>(hs, acc3, fln_w, fln_b, (float*)d_out, nullptr);
}

// round 11
// speedup vs baseline: 1.1145x; 1.1145x over previous
#include <cuda_runtime.h>
#include <cuda_fp16.h>
#include <cstdint>
#include <math.h>

#define NLY 8
#define Hd 768
#define Ed 1536
#define Nst 16
#define Rr 4
#define Kc 4
#define Cc 3
#define Bb 2
#define Ll 2048
#define Mrows (Bb*Ll)        // 4096
#define DBC (Rr+2*Nst)       // 36
#define TWO_E (2*Ed)         // 3072
#define MH ((size_t)Mrows*Hd)

// ======================= scratch (device globals) ============================
__device__ float g_hs  [Mrows*Hd];
__device__ float g_proj[Mrows*TWO_E];
__device__ float g_u   [Mrows*Ed];
__device__ float g_dbc [Mrows*DBC];
__device__ float g_acc3[3*Mrows*Hd];

// fp16 weights, transposed to [N,K]
__device__ __align__(16) __half g_wi [NLY*TWO_E*Hd];
__device__ __align__(16) __half g_wo [NLY*Hd*Ed];
__device__ __align__(16) __half g_wf [NLY*Cc*Hd*Hd];
// fp16 activations
__device__ __align__(16) __half g_xq [Mrows*Ed];    // x | ys
__device__ __align__(16) __half g_hq [Mrows*Hd];    // hs (fp16 copy)
__device__ __align__(16) __half g_yb3[3*Mrows*Hd];  // fractal stage 1
__device__ __align__(16) __half g_xq3[3*Mrows*Hd];  // fractal stage 2

// ======================= helpers =============================================
__device__ __forceinline__ uint32_t smem_u32(const void* p) {
    uint32_t a;
    asm("{ .reg .u64 t; cvta.to.shared.u64 t, %1; cvt.u32.u64 %0, t; }" : "=r"(a) : "l"(p));
    return a;
}
__device__ __forceinline__ void cp_async16(uint32_t dst, const void* src) {
    asm volatile("cp.async.cg.shared.global [%0], [%1], 16;" :: "r"(dst), "l"(src) : "memory");
}
__device__ __forceinline__ void cp_commit() {
    asm volatile("cp.async.commit_group;" ::: "memory");
}
__device__ __forceinline__ void ldm_x4(uint32_t* r, uint32_t addr) {
    asm volatile("ldmatrix.sync.aligned.m8n8.x4.shared.b16 {%0,%1,%2,%3}, [%4];"
                 : "=r"(r[0]), "=r"(r[1]), "=r"(r[2]), "=r"(r[3]) : "r"(addr));
}
__device__ __forceinline__ void mma_f16(float* d, const uint32_t* a, uint32_t b0, uint32_t b1) {
    asm volatile("mma.sync.aligned.m16n8k16.row.col.f32.f16.f16.f32 "
                 "{%0,%1,%2,%3}, {%4,%5,%6,%7}, {%8,%9}, {%0,%1,%2,%3};"
                 : "+f"(d[0]), "+f"(d[1]), "+f"(d[2]), "+f"(d[3])
                 : "r"(a[0]), "r"(a[1]), "r"(a[2]), "r"(a[3]), "r"(b0), "r"(b1));
}

// ======================= small kernels =======================================
__global__ void embed_kernel(const int* __restrict__ ids, const float* __restrict__ tok,
                             const float* __restrict__ pos, float* __restrict__ hs)
{
    int idx = blockIdx.x*blockDim.x + threadIdx.x;
    if (idx >= Mrows*Hd) return;
    int h = idx % Hd;
    int m = idx / Hd;
    int l = m % Ll;
    int id = ids[m];
    hs[idx] = tok[(size_t)id*Hd + h] + pos[(size_t)l*Hd + h];
}

// LayerNorm (+optional hs += (acc3[0]+acc3[1]+acc3[2])/6); output fp32 or fp16.
template<int HASACC, int OUTH>
__global__ void ln_fused(float* __restrict__ hs, const float* __restrict__ acc3,
                         const float* __restrict__ w, const float* __restrict__ b,
                         float* __restrict__ out32, __half* __restrict__ oh)
{
    int row = blockIdx.x;
    size_t base = (size_t)row*Hd;
    int tid = threadIdx.x;
    float v[3];
    float s = 0.f, s2 = 0.f;
    #pragma unroll
    for (int q = 0; q < 3; q++) {
        int i = tid + q*256;
        float t = hs[base + i];
        if (HASACC) {
            t += (0.5f/3.0f)*(acc3[base + i] + acc3[MH + base + i] + acc3[2*MH + base + i]);
            hs[base + i] = t;
        }
        v[q] = t;
        s += t; s2 += t*t;
    }
    #pragma unroll
    for (int o = 16; o; o >>= 1) {
        s  += __shfl_xor_sync(0xffffffffu, s,  o);
        s2 += __shfl_xor_sync(0xffffffffu, s2, o);
    }
    __shared__ float sa[8], sb[8];
    __shared__ float sh_mean, sh_inv;
    int wi = tid >> 5;
    if ((tid & 31) == 0) { sa[wi] = s; sb[wi] = s2; }
    __syncthreads();
    if (tid == 0) {
        float ts = 0.f, t2 = 0.f;
        #pragma unroll
        for (int i = 0; i < 8; i++) { ts += sa[i]; t2 += sb[i]; }
        float m  = ts / (float)Hd;
        float var = t2 / (float)Hd - m*m;
        sh_mean = m;
        sh_inv  = rsqrtf(var + 1e-5f);
    }
    __syncthreads();
    float mean = sh_mean, inv = sh_inv;
    #pragma unroll
    for (int q = 0; q < 3; q++) {
        int i = tid + q*256;
        float y = (v[q] - mean) * inv * w[i] + b[i];
        if (OUTH) oh[base + i] = __float2half(y);
        else      out32[base + i] = y;
    }
}

// W[z][K][N] fp32 -> T[z][N][K] fp16
__global__ void wtrans(const float* __restrict__ W, __half* __restrict__ T, int K, int N)
{
    __shared__ float t[32][33];
    size_t moff = (size_t)blockIdx.z * K * N;
    int nx = blockIdx.x*32, kx = blockIdx.y*32;
    int tx = threadIdx.x, ty = threadIdx.y;
    #pragma unroll
    for (int r = 0; r < 32; r += 8)
        t[ty + r][tx] = W[moff + (size_t)(kx + ty + r)*N + nx + tx];
    __syncthreads();
    #pragma unroll
    for (int r = 0; r < 32; r += 8)
        T[moff + (size_t)(nx + ty + r)*K + kx + tx] = __float2half(t[tx][ty + r]);
}

// ======================= fp16 mma GEMM (fat warp tiles, z-batched) ===========
// C = act( A[M,K] @ B[N,K]^T + bias [+add] ),  A,B fp16 K-major.
// CTA tile 128x128, BK=64, 4 warps (64x64 each), 3-stage cp.async, 2 CTAs/SM.
// blockIdx.z selects batch slice via strides Az/Bz/Oz/biasZ.
#define HSTAGE 32768
#define HSMEM  (3*HSTAGE)

template<int ACT, int HASADD, int OUTF32, int OUTH>
__global__ __launch_bounds__(128, 2)
void h_gemm(const __half* __restrict__ A, const __half* __restrict__ B,
            const float* __restrict__ bias, const float* __restrict__ add,
            float* __restrict__ C, __half* __restrict__ Oh, int M, int K, int N,
            size_t Az, size_t Bz, size_t Oz, size_t biasZ)
{
    extern __shared__ __align__(16) char smem[];
    const uint32_t sb0 = smem_u32(smem);
    int tid = threadIdx.x, lane = tid & 31, wid = tid >> 5;
    int zb = blockIdx.z;
    A += (size_t)zb*Az;  B += (size_t)zb*Bz;  bias += (size_t)zb*biasZ;
    int m0 = blockIdx.y << 7, n0 = blockIdx.x << 7;
    int wm = (wid >> 1) * 64, wn = (wid & 1) * 64;

    const __half* gsrc[2] = { A + (size_t)m0*K, B + (size_t)n0*K };

    const int cr0 = tid >> 3;
    const int cch = tid & 7;
    const int csw = cch ^ (cr0 & 7);
    const uint32_t cso = (uint32_t)(cr0*128 + csw*16);

    float acc[4][8][4];
    #pragma unroll
    for (int t = 0; t < 4; t++)
        #pragma unroll
        for (int j = 0; j < 8; j++)
            #pragma unroll
            for (int e = 0; e < 4; e++) acc[t][j][e] = 0.f;

    const int nt = K >> 6;

    #pragma unroll
    for (int p = 0; p < 2; p++) {
        uint32_t st = sb0 + p*HSTAGE;
        int k0 = p << 6;
        #pragma unroll
        for (int mat = 0; mat < 2; mat++) {
            const __half* src = gsrc[mat] + k0;
            uint32_t sbase = st + mat*16384u;
            #pragma unroll
            for (int q = 0; q < 8; q++) {
                int row = q*16 + cr0;
                cp_async16(sbase + cso + (uint32_t)(q*2048),
                           src + (size_t)row*K + cch*8);
            }
        }
        cp_commit();
    }

    int rA = (lane & 7) + ((lane >> 3) & 1)*8;
    int hi = lane >> 4;

    int stage = 0, pstage = 2;
    for (int i = 0; i < nt; i++) {
        if (i == nt - 1) asm volatile("cp.async.wait_group 0;" ::: "memory");
        else             asm volatile("cp.async.wait_group 1;" ::: "memory");
        __syncthreads();

        uint32_t stA = sb0 + stage*HSTAGE;
        uint32_t stB = stA + 16384u;

        #pragma unroll
        for (int s = 0; s < 4; s++) {
            int ck = 2*s + hi;
            uint32_t bf[4][4];
            #pragma unroll
            for (int u = 0; u < 4; u++) {
                int row = wn + u*16 + rA;
                uint32_t off = (uint32_t)(row*128 + ((ck ^ (row & 7))<<4));
                ldm_x4(bf[u], stB + off);
            }
            #pragma unroll
            for (int t = 0; t < 4; t++) {
                int row = wm + t*16 + rA;
                uint32_t off = (uint32_t)(row*128 + ((ck ^ (row & 7))<<4));
                uint32_t af[4];
                ldm_x4(af, stA + off);
                #pragma unroll
                for (int j = 0; j < 8; j++) {
                    int u = j >> 1, w = j & 1;
                    mma_f16(acc[t][j], af, bf[u][w], bf[u][w+2]);
                }
            }
        }

        if (i + 2 < nt) {
            uint32_t stp = sb0 + pstage*HSTAGE;
            int k0 = (i + 2) << 6;
            #pragma unroll
            for (int mat = 0; mat < 2; mat++) {
                const __half* src = gsrc[mat] + k0;
                uint32_t sbase = stp + mat*16384u;
                #pragma unroll
                for (int q = 0; q < 8; q++) {
                    int row = q*16 + cr0;
                    cp_async16(sbase + cso + (uint32_t)(q*2048),
                               src + (size_t)row*K + cch*8);
                }
            }
            cp_commit();
        }
        stage = (stage + 1 == 3) ? 0 : stage + 1;
        pstage = (pstage + 1 == 3) ? 0 : pstage + 1;
    }

    // ---- epilogue ----
    #pragma unroll
    for (int t = 0; t < 4; t++) {
        int mrow = m0 + wm + t*16 + (lane >> 2);
        #pragma unroll
        for (int j = 0; j < 8; j++) {
            int col = n0 + wn + j*8 + 2*(lane & 3);
            float b0 = bias[col], b1 = bias[col+1];
            #pragma unroll
            for (int half = 0; half < 2; half++) {
                int row = mrow + half*8;
                float v0 = acc[t][j][half*2+0] + b0;
                float v1 = acc[t][j][half*2+1] + b1;
                size_t o = (size_t)row*N + col;
                if (HASADD) { v0 += add[o]; v1 += add[o+1]; }
                if (ACT) {
                    v0 = v0 / (1.f + __expf(-v0));
                    v1 = v1 / (1.f + __expf(-v1));
                }
                if (OUTF32) *(float2*)(C + (size_t)zb*Oz + o) = make_float2(v0, v1);
                if (OUTH) {
                    __half2 hh;
                    hh.x = __float2half(v0);
                    hh.y = __float2half(v1);
                    *(__half2*)(Oh + (size_t)zb*Oz + o) = hh;
                }
            }
        }
    }
}

// ======================= conv / xproj / scan =================================
__global__ void conv_silu(const float* __restrict__ proj, const float* __restrict__ cw,
                          const float* __restrict__ cb, float* __restrict__ u)
{
    int idx = blockIdx.x*blockDim.x + threadIdx.x;
    if (idx >= Mrows*Ed) return;
    int e = idx % Ed;
    int m = idx / Ed;
    int l = m % Ll;
    float w0 = cw[e*4+0], w1 = cw[e*4+1], w2 = cw[e*4+2], w3 = cw[e*4+3];
    float v = cb[e];
    const float* base = proj + (size_t)m*TWO_E + e;
    if (l >= 3) v += base[-3*TWO_E]*w0;
    if (l >= 2) v += base[-2*TWO_E]*w1;
    if (l >= 1) v += base[-1*TWO_E]*w2;
    v += base[0]*w3;
    u[idx] = v / (1.f + __expf(-v));
}

__global__ __launch_bounds__(256)
void xproj_kernel(const float* __restrict__ u, const float* __restrict__ xw,
                  float* __restrict__ dbc)
{
    __shared__ float sxw[128*37];
    int tid = threadIdx.x, lane = tid & 31, w = tid >> 5;
    int m = blockIdx.x*8 + w;

    float acc[DBC];
    #pragma unroll
    for (int j = 0; j < DBC; j++) acc[j] = 0.f;

    for (int k0 = 0; k0 < Ed; k0 += 128) {
        __syncthreads();
        for (int i = tid; i < 128*DBC; i += 256) {
            int k = i / DBC, j = i - k*DBC;
            sxw[k*37 + j] = xw[(size_t)k0*DBC + i];
        }
        __syncthreads();
        #pragma unroll
        for (int q = 0; q < 4; q++) {
            float uv = u[(size_t)m*Ed + k0 + q*32 + lane];
            const float* row = &sxw[(q*32 + lane)*37];
            #pragma unroll
            for (int j = 0; j < DBC; j++) acc[j] += uv * row[j];
        }
    }
    #pragma unroll
    for (int j = 0; j < DBC; j++) {
        float s = acc[j];
        s += __shfl_xor_sync(0xffffffffu, s, 16);
        s += __shfl_xor_sync(0xffffffffu, s, 8);
        s += __shfl_xor_sync(0xffffffffu, s, 4);
        s += __shfl_xor_sync(0xffffffffu, s, 2);
        s += __shfl_xor_sync(0xffffffffu, s, 1);
        if (lane == 0) dbc[(size_t)m*DBC + j] = s;
    }
}

// Selective scan; ys emitted as fp16.
__global__ void scan_kernel(const float* __restrict__ u, const float* __restrict__ dbc,
                            const float* __restrict__ proj,
                            const float* __restrict__ dt_w, const float* __restrict__ dt_b,
                            const float* __restrict__ A_log, const float* __restrict__ Dv,
                            __half* __restrict__ ys)
{
    int gw = (blockIdx.x*blockDim.x + threadIdx.x) >> 5;
    int lane = threadIdx.x & 31;
    int ch = gw*2 + (lane >> 4);
    int b = ch / Ed, e = ch - b*Ed;
    int n = lane & 15;

    float Ac = -__expf(A_log[e*Nst + n]);
    float Dc = Dv[e];
    float w0 = dt_w[e], w1 = dt_w[Ed + e], w2 = dt_w[2*Ed + e], w3 = dt_w[3*Ed + e];
    float dtb = dt_b[e];

    const float* up = u    + (size_t)b*Ll*Ed + e;
    const float* dp = dbc  + (size_t)b*Ll*DBC;
    const float* gp = proj + (size_t)b*Ll*TWO_E + Ed + e;
    size_t ybase = (size_t)b*Ll*Ed + e;

    float h = 0.f;
    for (int t0 = 0; t0 < Ll; t0 += 4) {
        float p[4], uq[4];
        #pragma unroll
        for (int q = 0; q < 4; q++) {
            int t = t0 + q;
            const float* dr = dp + t*DBC;
            float4 d4 = *(const float4*)dr;
            float xdt = d4.x*w0 + d4.y*w1 + d4.z*w2 + d4.w*w3 + dtb;
            float dtv = (xdt > 20.f) ? xdt : log1pf(__expf(xdt));
            float uv = up[(size_t)t*Ed];
            float bt = dr[Rr + n];
            float ct = dr[Rr + Nst + n];
            h = h*__expf(dtv*Ac) + (dtv*uv)*bt;
            p[q] = h*ct;
            uq[q] = uv;
        }
        #pragma unroll
        for (int q = 0; q < 4; q++) {
            p[q] += __shfl_xor_sync(0xffffffffu, p[q], 8);
            p[q] += __shfl_xor_sync(0xffffffffu, p[q], 4);
            p[q] += __shfl_xor_sync(0xffffffffu, p[q], 2);
            p[q] += __shfl_xor_sync(0xffffffffu, p[q], 1);
        }
        if (n == 0) {
            #pragma unroll
            for (int q = 0; q < 4; q++) {
                int t = t0 + q;
                float g = gp[(size_t)t*TWO_E];
                float y = (p[q] + uq[q]*Dc) / (1.f + __expf(-g));
                ys[ybase + (size_t)t*Ed] = __float2half(y);
            }
        }
    }
}

// ======================= launch ==============================================
extern "C" void kernel_launch(void* const* d_in, const int* in_sizes, int n_in,
                              void* d_out, int out_size)
{
    const int*   ids     = (const int*)  d_in[0];
    const float* tok_emb = (const float*)d_in[1];
    const float* pos_emb = (const float*)d_in[2];
    const float* ln_w    = (const float*)d_in[3];
    const float* ln_b    = (const float*)d_in[4];
    const float* in_w    = (const float*)d_in[5];
    const float* in_b    = (const float*)d_in[6];
    const float* conv_w  = (const float*)d_in[7];
    const float* conv_b  = (const float*)d_in[8];
    const float* xproj_w = (const float*)d_in[9];
    const float* dt_w    = (const float*)d_in[10];
    const float* dt_b    = (const float*)d_in[11];
    const float* A_log   = (const float*)d_in[12];
    const float* Dv      = (const float*)d_in[13];
    const float* out_w   = (const float*)d_in[14];
    const float* out_b   = (const float*)d_in[15];
    const float* frac_w  = (const float*)d_in[16];
    const float* frac_b  = (const float*)d_in[17];
    const float* fln_w   = (const float*)d_in[18];
    const float* fln_b   = (const float*)d_in[19];

    float *hs, *proj, *u, *dbc, *acc3;
    __half *wi, *wo, *wf, *xq, *hq, *yb3, *xq3;
    cudaGetSymbolAddress((void**)&hs,   g_hs);
    cudaGetSymbolAddress((void**)&proj, g_proj);
    cudaGetSymbolAddress((void**)&u,    g_u);
    cudaGetSymbolAddress((void**)&dbc,  g_dbc);
    cudaGetSymbolAddress((void**)&acc3, g_acc3);
    cudaGetSymbolAddress((void**)&wi,   g_wi);
    cudaGetSymbolAddress((void**)&wo,   g_wo);
    cudaGetSymbolAddress((void**)&wf,   g_wf);
    cudaGetSymbolAddress((void**)&xq,   g_xq);
    cudaGetSymbolAddress((void**)&hq,   g_hq);
    cudaGetSymbolAddress((void**)&yb3,  g_yb3);
    cudaGetSymbolAddress((void**)&xq3,  g_xq3);

    cudaFuncSetAttribute(h_gemm<0,0,1,0>, cudaFuncAttributeMaxDynamicSharedMemorySize, HSMEM);
    cudaFuncSetAttribute(h_gemm<0,1,1,1>, cudaFuncAttributeMaxDynamicSharedMemorySize, HSMEM);
    cudaFuncSetAttribute(h_gemm<1,0,0,1>, cudaFuncAttributeMaxDynamicSharedMemorySize, HSMEM);
    cudaFuncSetAttribute(h_gemm<1,0,1,0>, cudaFuncAttributeMaxDynamicSharedMemorySize, HSMEM);

    // one-time weight prep
    wtrans<<<dim3(TWO_E/32, Hd/32, NLY), dim3(32,8)>>>(in_w, wi, Hd, TWO_E);
    wtrans<<<dim3(Hd/32, Ed/32, NLY),    dim3(32,8)>>>(out_w, wo, Ed, Hd);
    wtrans<<<dim3(Hd/32, Hd/32, NLY*Cc), dim3(32,8)>>>(frac_w, wf, Hd, Hd);

    embed_kernel<<<(Mrows*Hd + 255)/256, 256>>>(ids, tok_emb, pos_emb, hs);

    for (int l = 0; l < NLY; l++) {
        // x = LN(hs [+ sum(acc3)/6]) -> fp16
        if (l == 0)
            ln_fused<0,1><<<Mrows, 256>>>(hs, nullptr,
                ln_w + (size_t)l*Hd, ln_b + (size_t)l*Hd, nullptr, xq);
        else
            ln_fused<1,1><<<Mrows, 256>>>(hs, acc3,
                ln_w + (size_t)l*Hd, ln_b + (size_t)l*Hd, nullptr, xq);

        // proj = x @ in_w + in_b (fp32)
        h_gemm<0,0,1,0><<<dim3(TWO_E/128, Mrows/128, 1), 128, HSMEM>>>(
            xq, wi + (size_t)l*TWO_E*Hd, in_b + (size_t)l*TWO_E, nullptr,
            proj, nullptr, Mrows, Hd, TWO_E, 0, 0, 0, 0);

        conv_silu<<<(Mrows*Ed + 255)/256, 256>>>(
            proj, conv_w + (size_t)l*Ed*Kc, conv_b + (size_t)l*Ed, u);

        xproj_kernel<<<Mrows/8, 256>>>(u, xproj_w + (size_t)l*Ed*DBC, dbc);

        // scan -> ys fp16 (into xq)
        scan_kernel<<<192, 256>>>(u, dbc, proj,
            dt_w + (size_t)l*Rr*Ed, dt_b + (size_t)l*Ed,
            A_log + (size_t)l*Ed*Nst, Dv + (size_t)l*Ed, xq);

        // hs = ys @ out_w + out_b + hs (fp32) ; also hq = fp16(hs)
        h_gemm<0,1,1,1><<<dim3(Hd/128, Mrows/128, 1), 128, HSMEM>>>(
            xq, wo + (size_t)l*Hd*Ed, out_b + (size_t)l*Hd, hs,
            hs, hq, Mrows, Ed, Hd, 0, 0, 0, 0);

        // fractal: z-batched over the 3 independent chains
        const __half* fwl = wf + (size_t)l*Cc*Hd*Hd;
        const float*  fbl = frac_b + (size_t)l*Cc*Hd;
        h_gemm<1,0,0,1><<<dim3(Hd/128, Mrows/128, Cc), 128, HSMEM>>>(
            hq, fwl, fbl, nullptr, nullptr, yb3,
            Mrows, Hd, Hd, 0, (size_t)Hd*Hd, MH, Hd);
        h_gemm<1,0,0,1><<<dim3(Hd/128, Mrows/128, Cc), 128, HSMEM>>>(
            yb3, fwl, fbl, nullptr, nullptr, xq3,
            Mrows, Hd, Hd, MH, (size_t)Hd*Hd, MH, Hd);
        h_gemm<1,0,1,0><<<dim3(Hd/128, Mrows/128, Cc), 128, HSMEM>>>(
            xq3, fwl, fbl, nullptr, acc3, nullptr,
            Mrows, Hd, Hd, MH, (size_t)Hd*Hd, MH, Hd);
    }

    // final: hs += sum(acc3)/6 ; out = LN(hs)
    ln_fused<1,0><<<Mrows, 256>>>(hs, acc3, fln_w, fln_b, (float*)d_out, nullptr);
}

// round 12
// speedup vs baseline: 1.1430x; 1.0256x over previous
#include <cuda_runtime.h>
#include <cuda_fp16.h>
#include <cstdint>
#include <math.h>

#define NLY 8
#define Hd 768
#define Ed 1536
#define Nst 16
#define Rr 4
#define Kc 4
#define Cc 3
#define Bb 2
#define Ll 2048
#define Mrows (Bb*Ll)        // 4096
#define DBC (Rr+2*Nst)       // 36
#define TWO_E (2*Ed)         // 3072
#define MH ((size_t)Mrows*Hd)

// ======================= scratch (device globals) ============================
__device__ float g_hs  [Mrows*Hd];
__device__ float g_proj[Mrows*TWO_E];
__device__ float g_u   [Mrows*Ed];
__device__ float g_dbc [Mrows*DBC];
__device__ float g_acc3[3*Mrows*Hd];

// fp16 weights, transposed to [N,K]
__device__ __align__(16) __half g_wi [NLY*TWO_E*Hd];
__device__ __align__(16) __half g_wo [NLY*Hd*Ed];
__device__ __align__(16) __half g_wf [NLY*Cc*Hd*Hd];
// fp16 activations
__device__ __align__(16) __half g_xq [Mrows*Ed];    // x | ys
__device__ __align__(16) __half g_hq [Mrows*Hd];    // hs (fp16 copy)
__device__ __align__(16) __half g_yb3[3*Mrows*Hd];  // fractal stage 1
__device__ __align__(16) __half g_xq3[3*Mrows*Hd];  // fractal stage 2

// ======================= helpers =============================================
__device__ __forceinline__ uint32_t smem_u32(const void* p) {
    uint32_t a;
    asm("{ .reg .u64 t; cvta.to.shared.u64 t, %1; cvt.u32.u64 %0, t; }" : "=r"(a) : "l"(p));
    return a;
}
__device__ __forceinline__ void cp_async16(uint32_t dst, const void* src) {
    asm volatile("cp.async.cg.shared.global [%0], [%1], 16;" :: "r"(dst), "l"(src) : "memory");
}
__device__ __forceinline__ void cp_commit() {
    asm volatile("cp.async.commit_group;" ::: "memory");
}
__device__ __forceinline__ void ldm_x4(uint32_t* r, uint32_t addr) {
    asm volatile("ldmatrix.sync.aligned.m8n8.x4.shared.b16 {%0,%1,%2,%3}, [%4];"
                 : "=r"(r[0]), "=r"(r[1]), "=r"(r[2]), "=r"(r[3]) : "r"(addr));
}
__device__ __forceinline__ void mma_f16(float* d, const uint32_t* a, uint32_t b0, uint32_t b1) {
    asm volatile("mma.sync.aligned.m16n8k16.row.col.f32.f16.f16.f32 "
                 "{%0,%1,%2,%3}, {%4,%5,%6,%7}, {%8,%9}, {%0,%1,%2,%3};"
                 : "+f"(d[0]), "+f"(d[1]), "+f"(d[2]), "+f"(d[3])
                 : "r"(a[0]), "r"(a[1]), "r"(a[2]), "r"(a[3]), "r"(b0), "r"(b1));
}

// ======================= small kernels =======================================
__global__ void embed_kernel(const int* __restrict__ ids, const float* __restrict__ tok,
                             const float* __restrict__ pos, float* __restrict__ hs)
{
    int idx = blockIdx.x*blockDim.x + threadIdx.x;
    if (idx >= Mrows*Hd) return;
    int h = idx % Hd;
    int m = idx / Hd;
    int l = m % Ll;
    int id = ids[m];
    hs[idx] = tok[(size_t)id*Hd + h] + pos[(size_t)l*Hd + h];
}

// LayerNorm (+optional hs += (acc3[0]+acc3[1]+acc3[2])/6); output fp32 or fp16.
template<int HASACC, int OUTH>
__global__ void ln_fused(float* __restrict__ hs, const float* __restrict__ acc3,
                         const float* __restrict__ w, const float* __restrict__ b,
                         float* __restrict__ out32, __half* __restrict__ oh)
{
    int row = blockIdx.x;
    size_t base = (size_t)row*Hd;
    int tid = threadIdx.x;
    float v[3];
    float s = 0.f, s2 = 0.f;
    #pragma unroll
    for (int q = 0; q < 3; q++) {
        int i = tid + q*256;
        float t = hs[base + i];
        if (HASACC) {
            t += (0.5f/3.0f)*(acc3[base + i] + acc3[MH + base + i] + acc3[2*MH + base + i]);
            hs[base + i] = t;
        }
        v[q] = t;
        s += t; s2 += t*t;
    }
    #pragma unroll
    for (int o = 16; o; o >>= 1) {
        s  += __shfl_xor_sync(0xffffffffu, s,  o);
        s2 += __shfl_xor_sync(0xffffffffu, s2, o);
    }
    __shared__ float sa[8], sb[8];
    __shared__ float sh_mean, sh_inv;
    int wi = tid >> 5;
    if ((tid & 31) == 0) { sa[wi] = s; sb[wi] = s2; }
    __syncthreads();
    if (tid == 0) {
        float ts = 0.f, t2 = 0.f;
        #pragma unroll
        for (int i = 0; i < 8; i++) { ts += sa[i]; t2 += sb[i]; }
        float m  = ts / (float)Hd;
        float var = t2 / (float)Hd - m*m;
        sh_mean = m;
        sh_inv  = rsqrtf(var + 1e-5f);
    }
    __syncthreads();
    float mean = sh_mean, inv = sh_inv;
    #pragma unroll
    for (int q = 0; q < 3; q++) {
        int i = tid + q*256;
        float y = (v[q] - mean) * inv * w[i] + b[i];
        if (OUTH) oh[base + i] = __float2half(y);
        else      out32[base + i] = y;
    }
}

// W[z][K][N] fp32 -> T[z][N][K] fp16
__global__ void wtrans(const float* __restrict__ W, __half* __restrict__ T, int K, int N)
{
    __shared__ float t[32][33];
    size_t moff = (size_t)blockIdx.z * K * N;
    int nx = blockIdx.x*32, kx = blockIdx.y*32;
    int tx = threadIdx.x, ty = threadIdx.y;
    #pragma unroll
    for (int r = 0; r < 32; r += 8)
        t[ty + r][tx] = W[moff + (size_t)(kx + ty + r)*N + nx + tx];
    __syncthreads();
    #pragma unroll
    for (int r = 0; r < 32; r += 8)
        T[moff + (size_t)(nx + ty + r)*K + kx + tx] = __float2half(t[tx][ty + r]);
}

// ======================= fp16 mma GEMM (fat warp tiles, z-batched) ===========
// C = act( A[M,K] @ B[N,K]^T + bias [+add] ),  A,B fp16 K-major.
// CTA tile 128x128, BK=64, 4 warps (64x64 each), 3-stage cp.async, 2 CTAs/SM.
// Prefetch is issued BEFORE the compute phases (2 tiles of latency slack).
#define HSTAGE 32768
#define HSMEM  (3*HSTAGE)

template<int ACT, int HASADD, int OUTF32, int OUTH>
__global__ __launch_bounds__(128, 2)
void h_gemm(const __half* __restrict__ A, const __half* __restrict__ B,
            const float* __restrict__ bias, const float* __restrict__ add,
            float* __restrict__ C, __half* __restrict__ Oh, int M, int K, int N,
            size_t Az, size_t Bz, size_t Oz, size_t biasZ)
{
    extern __shared__ __align__(16) char smem[];
    const uint32_t sb0 = smem_u32(smem);
    int tid = threadIdx.x, lane = tid & 31, wid = tid >> 5;
    int zb = blockIdx.z;
    A += (size_t)zb*Az;  B += (size_t)zb*Bz;  bias += (size_t)zb*biasZ;
    int m0 = blockIdx.y << 7, n0 = blockIdx.x << 7;
    int wm = (wid >> 1) * 64, wn = (wid & 1) * 64;

    const __half* gsrc[2] = { A + (size_t)m0*K, B + (size_t)n0*K };

    const int cr0 = tid >> 3;
    const int cch = tid & 7;
    const int csw = cch ^ (cr0 & 7);
    const uint32_t cso = (uint32_t)(cr0*128 + csw*16);

    float acc[4][8][4];
    #pragma unroll
    for (int t = 0; t < 4; t++)
        #pragma unroll
        for (int j = 0; j < 8; j++)
            #pragma unroll
            for (int e = 0; e < 4; e++) acc[t][j][e] = 0.f;

    const int nt = K >> 6;

    #pragma unroll
    for (int p = 0; p < 2; p++) {
        uint32_t st = sb0 + p*HSTAGE;
        int k0 = p << 6;
        #pragma unroll
        for (int mat = 0; mat < 2; mat++) {
            const __half* src = gsrc[mat] + k0;
            uint32_t sbase = st + mat*16384u;
            #pragma unroll
            for (int q = 0; q < 8; q++) {
                int row = q*16 + cr0;
                cp_async16(sbase + cso + (uint32_t)(q*2048),
                           src + (size_t)row*K + cch*8);
            }
        }
        cp_commit();
    }

    int rA = (lane & 7) + ((lane >> 3) & 1)*8;
    int hi = lane >> 4;

    int stage = 0, pstage = 2;
    for (int i = 0; i < nt; i++) {
        if (i == nt - 1) asm volatile("cp.async.wait_group 0;" ::: "memory");
        else             asm volatile("cp.async.wait_group 1;" ::: "memory");
        __syncthreads();

        // ---- issue prefetch for tile i+2 FIRST (max latency slack) ----
        if (i + 2 < nt) {
            uint32_t stp = sb0 + pstage*HSTAGE;
            int k0 = (i + 2) << 6;
            #pragma unroll
            for (int mat = 0; mat < 2; mat++) {
                const __half* src = gsrc[mat] + k0;
                uint32_t sbase = stp + mat*16384u;
                #pragma unroll
                for (int q = 0; q < 8; q++) {
                    int row = q*16 + cr0;
                    cp_async16(sbase + cso + (uint32_t)(q*2048),
                               src + (size_t)row*K + cch*8);
                }
            }
            cp_commit();
        }

        uint32_t stA = sb0 + stage*HSTAGE;
        uint32_t stB = stA + 16384u;

        #pragma unroll
        for (int s = 0; s < 4; s++) {
            int ck = 2*s + hi;
            uint32_t bf[4][4];
            #pragma unroll
            for (int u = 0; u < 4; u++) {
                int row = wn + u*16 + rA;
                uint32_t off = (uint32_t)(row*128 + ((ck ^ (row & 7))<<4));
                ldm_x4(bf[u], stB + off);
            }
            #pragma unroll
            for (int t = 0; t < 4; t++) {
                int row = wm + t*16 + rA;
                uint32_t off = (uint32_t)(row*128 + ((ck ^ (row & 7))<<4));
                uint32_t af[4];
                ldm_x4(af, stA + off);
                #pragma unroll
                for (int j = 0; j < 8; j++) {
                    int u = j >> 1, w = j & 1;
                    mma_f16(acc[t][j], af, bf[u][w], bf[u][w+2]);
                }
            }
        }

        stage = (stage + 1 == 3) ? 0 : stage + 1;
        pstage = (pstage + 1 == 3) ? 0 : pstage + 1;
    }

    // ---- epilogue ----
    #pragma unroll
    for (int t = 0; t < 4; t++) {
        int mrow = m0 + wm + t*16 + (lane >> 2);
        #pragma unroll
        for (int j = 0; j < 8; j++) {
            int col = n0 + wn + j*8 + 2*(lane & 3);
            float b0 = bias[col], b1 = bias[col+1];
            #pragma unroll
            for (int half = 0; half < 2; half++) {
                int row = mrow + half*8;
                float v0 = acc[t][j][half*2+0] + b0;
                float v1 = acc[t][j][half*2+1] + b1;
                size_t o = (size_t)row*N + col;
                if (HASADD) { v0 += add[o]; v1 += add[o+1]; }
                if (ACT) {
                    v0 = v0 / (1.f + __expf(-v0));
                    v1 = v1 / (1.f + __expf(-v1));
                }
                if (OUTF32) *(float2*)(C + (size_t)zb*Oz + o) = make_float2(v0, v1);
                if (OUTH) {
                    __half2 hh;
                    hh.x = __float2half(v0);
                    hh.y = __float2half(v1);
                    *(__half2*)(Oh + (size_t)zb*Oz + o) = hh;
                }
            }
        }
    }
}

// ======================= fused conv_silu + xproj =============================
// Block = 8 rows. Phase A: u = silu(dwconv(proj)) into smem + gmem.
// Phase B: dbc[m,36] = u[m,:] @ xw (weights staged per 128-k chunk).
// dyn smem: u_s 8*1536*4 = 49152 + xw stage 128*37*4 = 18944  => 68096 B
#define CXSMEM (8*Ed*4 + 128*37*4)

__global__ __launch_bounds__(256)
void convxp_kernel(const float* __restrict__ proj, const float* __restrict__ cw,
                   const float* __restrict__ cb, const float* __restrict__ xw,
                   float* __restrict__ u, float* __restrict__ dbc)
{
    extern __shared__ float smf[];
    float* u_s = smf;                  // [8][1536]
    float* sxw = smf + 8*Ed;           // [128][37]
    int tid = threadIdx.x, lane = tid & 31, w = tid >> 5;
    int m0 = blockIdx.x*8;

    // ---- Phase A: conv + silu ----
    for (int idx = tid; idx < 8*Ed; idx += 256) {
        int r = idx / Ed, e = idx - (idx/Ed)*Ed;
        int m = m0 + r;
        int l = m % Ll;
        float w0 = cw[e*4+0], w1 = cw[e*4+1], w2 = cw[e*4+2], w3 = cw[e*4+3];
        float v = cb[e];
        const float* base = proj + (size_t)m*TWO_E + e;
        if (l >= 3) v += base[-3*TWO_E]*w0;
        if (l >= 2) v += base[-2*TWO_E]*w1;
        if (l >= 1) v += base[-1*TWO_E]*w2;
        v += base[0]*w3;
        float s = v / (1.f + __expf(-v));
        u_s[idx] = s;
        u[(size_t)m*Ed + e] = s;
    }

    // ---- Phase B: xproj from smem ----
    float acc[DBC];
    #pragma unroll
    for (int j = 0; j < DBC; j++) acc[j] = 0.f;

    for (int k0 = 0; k0 < Ed; k0 += 128) {
        __syncthreads();
        for (int i = tid; i < 128*DBC; i += 256) {
            int k = i / DBC, j = i - k*DBC;
            sxw[k*37 + j] = xw[(size_t)k0*DBC + i];
        }
        __syncthreads();
        #pragma unroll
        for (int q = 0; q < 4; q++) {
            float uv = u_s[w*Ed + k0 + q*32 + lane];
            const float* row = &sxw[(q*32 + lane)*37];
            #pragma unroll
            for (int j = 0; j < DBC; j++) acc[j] += uv * row[j];
        }
    }
    #pragma unroll
    for (int j = 0; j < DBC; j++) {
        float s = acc[j];
        s += __shfl_xor_sync(0xffffffffu, s, 16);
        s += __shfl_xor_sync(0xffffffffu, s, 8);
        s += __shfl_xor_sync(0xffffffffu, s, 4);
        s += __shfl_xor_sync(0xffffffffu, s, 2);
        s += __shfl_xor_sync(0xffffffffu, s, 1);
        if (lane == 0) dbc[(size_t)(m0 + w)*DBC + j] = s;
    }
}

// Selective scan; ys emitted as fp16.
__global__ void scan_kernel(const float* __restrict__ u, const float* __restrict__ dbc,
                            const float* __restrict__ proj,
                            const float* __restrict__ dt_w, const float* __restrict__ dt_b,
                            const float* __restrict__ A_log, const float* __restrict__ Dv,
                            __half* __restrict__ ys)
{
    int gw = (blockIdx.x*blockDim.x + threadIdx.x) >> 5;
    int lane = threadIdx.x & 31;
    int ch = gw*2 + (lane >> 4);
    int b = ch / Ed, e = ch - b*Ed;
    int n = lane & 15;

    float Ac = -__expf(A_log[e*Nst + n]);
    float Dc = Dv[e];
    float w0 = dt_w[e], w1 = dt_w[Ed + e], w2 = dt_w[2*Ed + e], w3 = dt_w[3*Ed + e];
    float dtb = dt_b[e];

    const float* up = u    + (size_t)b*Ll*Ed + e;
    const float* dp = dbc  + (size_t)b*Ll*DBC;
    const float* gp = proj + (size_t)b*Ll*TWO_E + Ed + e;
    size_t ybase = (size_t)b*Ll*Ed + e;

    float h = 0.f;
    for (int t0 = 0; t0 < Ll; t0 += 4) {
        float p[4], uq[4];
        #pragma unroll
        for (int q = 0; q < 4; q++) {
            int t = t0 + q;
            const float* dr = dp + t*DBC;
            float4 d4 = *(const float4*)dr;
            float xdt = d4.x*w0 + d4.y*w1 + d4.z*w2 + d4.w*w3 + dtb;
            float dtv = (xdt > 20.f) ? xdt : log1pf(__expf(xdt));
            float uv = up[(size_t)t*Ed];
            float bt = dr[Rr + n];
            float ct = dr[Rr + Nst + n];
            h = h*__expf(dtv*Ac) + (dtv*uv)*bt;
            p[q] = h*ct;
            uq[q] = uv;
        }
        #pragma unroll
        for (int q = 0; q < 4; q++) {
            p[q] += __shfl_xor_sync(0xffffffffu, p[q], 8);
            p[q] += __shfl_xor_sync(0xffffffffu, p[q], 4);
            p[q] += __shfl_xor_sync(0xffffffffu, p[q], 2);
            p[q] += __shfl_xor_sync(0xffffffffu, p[q], 1);
        }
        if (n == 0) {
            #pragma unroll
            for (int q = 0; q < 4; q++) {
                int t = t0 + q;
                float g = gp[(size_t)t*TWO_E];
                float y = (p[q] + uq[q]*Dc) / (1.f + __expf(-g));
                ys[ybase + (size_t)t*Ed] = __float2half(y);
            }
        }
    }
}

// ======================= launch ==============================================
extern "C" void kernel_launch(void* const* d_in, const int* in_sizes, int n_in,
                              void* d_out, int out_size)
{
    const int*   ids     = (const int*)  d_in[0];
    const float* tok_emb = (const float*)d_in[1];
    const float* pos_emb = (const float*)d_in[2];
    const float* ln_w    = (const float*)d_in[3];
    const float* ln_b    = (const float*)d_in[4];
    const float* in_w    = (const float*)d_in[5];
    const float* in_b    = (const float*)d_in[6];
    const float* conv_w  = (const float*)d_in[7];
    const float* conv_b  = (const float*)d_in[8];
    const float* xproj_w = (const float*)d_in[9];
    const float* dt_w    = (const float*)d_in[10];
    const float* dt_b    = (const float*)d_in[11];
    const float* A_log   = (const float*)d_in[12];
    const float* Dv      = (const float*)d_in[13];
    const float* out_w   = (const float*)d_in[14];
    const float* out_b   = (const float*)d_in[15];
    const float* frac_w  = (const float*)d_in[16];
    const float* frac_b  = (const float*)d_in[17];
    const float* fln_w   = (const float*)d_in[18];
    const float* fln_b   = (const float*)d_in[19];

    float *hs, *proj, *u, *dbc, *acc3;
    __half *wi, *wo, *wf, *xq, *hq, *yb3, *xq3;
    cudaGetSymbolAddress((void**)&hs,   g_hs);
    cudaGetSymbolAddress((void**)&proj, g_proj);
    cudaGetSymbolAddress((void**)&u,    g_u);
    cudaGetSymbolAddress((void**)&dbc,  g_dbc);
    cudaGetSymbolAddress((void**)&acc3, g_acc3);
    cudaGetSymbolAddress((void**)&wi,   g_wi);
    cudaGetSymbolAddress((void**)&wo,   g_wo);
    cudaGetSymbolAddress((void**)&wf,   g_wf);
    cudaGetSymbolAddress((void**)&xq,   g_xq);
    cudaGetSymbolAddress((void**)&hq,   g_hq);
    cudaGetSymbolAddress((void**)&yb3,  g_yb3);
    cudaGetSymbolAddress((void**)&xq3,  g_xq3);

    cudaFuncSetAttribute(h_gemm<0,0,1,0>, cudaFuncAttributeMaxDynamicSharedMemorySize, HSMEM);
    cudaFuncSetAttribute(h_gemm<0,1,1,1>, cudaFuncAttributeMaxDynamicSharedMemorySize, HSMEM);
    cudaFuncSetAttribute(h_gemm<1,0,0,1>, cudaFuncAttributeMaxDynamicSharedMemorySize, HSMEM);
    cudaFuncSetAttribute(h_gemm<1,0,1,0>, cudaFuncAttributeMaxDynamicSharedMemorySize, HSMEM);
    cudaFuncSetAttribute(convxp_kernel, cudaFuncAttributeMaxDynamicSharedMemorySize, CXSMEM);

    // one-time weight prep
    wtrans<<<dim3(TWO_E/32, Hd/32, NLY), dim3(32,8)>>>(in_w, wi, Hd, TWO_E);
    wtrans<<<dim3(Hd/32, Ed/32, NLY),    dim3(32,8)>>>(out_w, wo, Ed, Hd);
    wtrans<<<dim3(Hd/32, Hd/32, NLY*Cc), dim3(32,8)>>>(frac_w, wf, Hd, Hd);

    embed_kernel<<<(Mrows*Hd + 255)/256, 256>>>(ids, tok_emb, pos_emb, hs);

    for (int l = 0; l < NLY; l++) {
        // x = LN(hs [+ sum(acc3)/6]) -> fp16
        if (l == 0)
            ln_fused<0,1><<<Mrows, 256>>>(hs, nullptr,
                ln_w + (size_t)l*Hd, ln_b + (size_t)l*Hd, nullptr, xq);
        else
            ln_fused<1,1><<<Mrows, 256>>>(hs, acc3,
                ln_w + (size_t)l*Hd, ln_b + (size_t)l*Hd, nullptr, xq);

        // proj = x @ in_w + in_b (fp32)
        h_gemm<0,0,1,0><<<dim3(TWO_E/128, Mrows/128, 1), 128, HSMEM>>>(
            xq, wi + (size_t)l*TWO_E*Hd, in_b + (size_t)l*TWO_E, nullptr,
            proj, nullptr, Mrows, Hd, TWO_E, 0, 0, 0, 0);

        // u = silu(conv(proj)), dbc = u @ xproj_w  (fused)
        convxp_kernel<<<Mrows/8, 256, CXSMEM>>>(
            proj, conv_w + (size_t)l*Ed*Kc, conv_b + (size_t)l*Ed,
            xproj_w + (size_t)l*Ed*DBC, u, dbc);

        // scan -> ys fp16 (into xq)
        scan_kernel<<<192, 256>>>(u, dbc, proj,
            dt_w + (size_t)l*Rr*Ed, dt_b + (size_t)l*Ed,
            A_log + (size_t)l*Ed*Nst, Dv + (size_t)l*Ed, xq);

        // hs = ys @ out_w + out_b + hs (fp32) ; also hq = fp16(hs)
        h_gemm<0,1,1,1><<<dim3(Hd/128, Mrows/128, 1), 128, HSMEM>>>(
            xq, wo + (size_t)l*Hd*Ed, out_b + (size_t)l*Hd, hs,
            hs, hq, Mrows, Ed, Hd, 0, 0, 0, 0);

        // fractal: z-batched over the 3 independent chains
        const __half* fwl = wf + (size_t)l*Cc*Hd*Hd;
        const float*  fbl = frac_b + (size_t)l*Cc*Hd;
        h_gemm<1,0,0,1><<<dim3(Hd/128, Mrows/128, Cc), 128, HSMEM>>>(
            hq, fwl, fbl, nullptr, nullptr, yb3,
            Mrows, Hd, Hd, 0, (size_t)Hd*Hd, MH, Hd);
        h_gemm<1,0,0,1><<<dim3(Hd/128, Mrows/128, Cc), 128, HSMEM>>>(
            yb3, fwl, fbl, nullptr, nullptr, xq3,
            Mrows, Hd, Hd, MH, (size_t)Hd*Hd, MH, Hd);
        h_gemm<1,0,1,0><<<dim3(Hd/128, Mrows/128, Cc), 128, HSMEM>>>(
            xq3, fwl, fbl, nullptr, acc3, nullptr,
            Mrows, Hd, Hd, MH, (size_t)Hd*Hd, MH, Hd);
    }

    // final: hs += sum(acc3)/6 ; out = LN(hs)
    ln_fused<1,0><<<Mrows, 256>>>(hs, acc3, fln_w, fln_b, (float*)d_out, nullptr);
}